// round 2
// baseline (speedup 1.0000x reference)
#include <cuda_runtime.h>
#include <cuda_bf16.h>

// Problem constants (fixed by setup_inputs)
#define BN 8192      // batch
#define DD 128       // embedding dim
#define TMARGIN 1.0f

// Mining tile config
#define BI 128
#define BJ 128
#define JSPLIT 4
#define JCH (BN / JSPLIT)   // 2048 j-range per block

// ---------------- scratch (device globals; no allocation allowed) ----------------
__device__ float        g_sq[BN];
__device__ unsigned int g_negmin[BN];   // float bits of min negative distance (d>=0 -> uint order == float order)
__device__ float        g_total;
__device__ int          g_count;
__device__ int          g_lab32[BN];
__device__ int          g_is64;

// ---------------- label dtype detection ----------------
// If labels are int64 (values in [0,1024)), every odd 32-bit word of the first
// 128 pairs is 0. If int32, odd words are random labels (all-zero ~ impossible).
// Both layouts have >= 32KB, so reading the first 256 int32 words is in-bounds.
__global__ void detect_kernel(const int* __restrict__ raw) {
    int lane = threadIdx.x;          // 128 threads, one odd word each
    int v = raw[2 * lane + 1];
    unsigned any = __ballot_sync(0xffffffffu, v != 0);
#pragma unroll
    for (int off = 32; off < 128; off <<= 1) { }  // (single warp-group handled below)
    __shared__ int s_any;
    if (threadIdx.x == 0) s_any = 0;
    __syncthreads();
    if ((threadIdx.x & 31) == 0 && any) atomicOr(&s_any, 1);
    __syncthreads();
    if (threadIdx.x == 0) g_is64 = (s_any == 0) ? 1 : 0;
}

// ---------------- init: neg_min=+inf, accumulators=0, labels -> int32 ----------------
__global__ void init_kernel(const void* __restrict__ labraw) {
    int i = blockIdx.x * blockDim.x + threadIdx.x;
    if (i < BN) {
        g_negmin[i] = 0x7f800000u;   // +inf
        if (g_is64)
            g_lab32[i] = (int)((const long long*)labraw)[i];
        else
            g_lab32[i] = ((const int*)labraw)[i];
    }
    if (i == 0) { g_total = 0.f; g_count = 0; }
}

// ---------------- squared norms: one warp per row ----------------
__global__ void sq_kernel(const float* __restrict__ E) {
    int warp = (blockIdx.x * blockDim.x + threadIdx.x) >> 5;
    int lane = threadIdx.x & 31;
    if (warp >= BN) return;
    const float* row = E + (size_t)warp * DD;
    float v0 = row[lane], v1 = row[lane + 32], v2 = row[lane + 64], v3 = row[lane + 96];
    float s = v0 * v0 + v1 * v1 + v2 * v2 + v3 * v3;
#pragma unroll
    for (int off = 16; off; off >>= 1) s += __shfl_xor_sync(0xffffffffu, s, off);
    if (lane == 0) g_sq[warp] = s;
}

// ---------------- fused Gram-GEMM + label-masked row-min ----------------
// grid: (BN/BI, JSPLIT), block 256 threads (16x16), 8x8 micro-tile per thread.
__global__ __launch_bounds__(256, 2)
void negmine_kernel(const float* __restrict__ E) {
    __shared__ float As[16][BI];   // transposed chunks: As[k][i]
    __shared__ float Bs[16][BJ];
    __shared__ int   sLabI[BI];
    __shared__ int   sLabJ[BJ];
    __shared__ float sSqI[BI];
    __shared__ float sSqJ[BJ];

    const int tid = threadIdx.x;
    const int tx = tid & 15;
    const int ty = tid >> 4;
    const int i0 = blockIdx.x * BI;
    const int jbase = blockIdx.y * JCH;

    if (tid < BI) {
        sLabI[tid] = g_lab32[i0 + tid];
        sSqI[tid]  = g_sq[i0 + tid];
    }

    float rmin[8];
#pragma unroll
    for (int r = 0; r < 8; r++) rmin[r] = __int_as_float(0x7f800000);

    for (int jt = 0; jt < JCH / BJ; jt++) {
        const int j0 = jbase + jt * BJ;
        __syncthreads();   // protect sLabJ/sSqJ & smem tiles from previous iteration readers
        if (tid < BJ) {
            sLabJ[tid] = g_lab32[j0 + tid];
            sSqJ[tid]  = g_sq[j0 + tid];
        }

        float acc[8][8];
#pragma unroll
        for (int a = 0; a < 8; a++)
#pragma unroll
            for (int b = 0; b < 8; b++) acc[a][b] = 0.f;

#pragma unroll
        for (int kc = 0; kc < DD / 16; kc++) {
            const int k0 = kc * 16;
            __syncthreads();
            // Load 128x16 chunks of A-tile and B-tile, stored K-major (transposed).
#pragma unroll
            for (int q = 0; q < 2; q++) {
                int f   = tid * 2 + q;     // 0..511
                int row = f >> 2;          // 0..127
                int kk  = (f & 3) * 4;     // 0,4,8,12
                float4 va = *reinterpret_cast<const float4*>(&E[(size_t)(i0 + row) * DD + k0 + kk]);
                As[kk + 0][row] = va.x; As[kk + 1][row] = va.y;
                As[kk + 2][row] = va.z; As[kk + 3][row] = va.w;
                float4 vb = *reinterpret_cast<const float4*>(&E[(size_t)(j0 + row) * DD + k0 + kk]);
                Bs[kk + 0][row] = vb.x; Bs[kk + 1][row] = vb.y;
                Bs[kk + 2][row] = vb.z; Bs[kk + 3][row] = vb.w;
            }
            __syncthreads();
#pragma unroll
            for (int k = 0; k < 16; k++) {
                float4 a0 = *reinterpret_cast<const float4*>(&As[k][ty * 8]);
                float4 a1 = *reinterpret_cast<const float4*>(&As[k][ty * 8 + 4]);
                float4 b0 = *reinterpret_cast<const float4*>(&Bs[k][tx * 8]);
                float4 b1 = *reinterpret_cast<const float4*>(&Bs[k][tx * 8 + 4]);
                float av[8] = {a0.x, a0.y, a0.z, a0.w, a1.x, a1.y, a1.z, a1.w};
                float bv[8] = {b0.x, b0.y, b0.z, b0.w, b1.x, b1.y, b1.z, b1.w};
#pragma unroll
                for (int r = 0; r < 8; r++)
#pragma unroll
                    for (int c = 0; c < 8; c++)
                        acc[r][c] += av[r] * bv[c];
            }
        }

        // Epilogue: distance + relu + label-masked min
#pragma unroll
        for (int r = 0; r < 8; r++) {
            const int   li = sLabI[ty * 8 + r];
            const float si = sSqI[ty * 8 + r];
#pragma unroll
            for (int c = 0; c < 8; c++) {
                float dd = fmaxf(si + sSqJ[tx * 8 + c] - 2.f * acc[r][c], 0.f);
                if (li != sLabJ[tx * 8 + c]) rmin[r] = fminf(rmin[r], dd);
            }
        }
    }

    // Reduce min across the 16 tx lanes (they share the same anchor rows)
#pragma unroll
    for (int off = 1; off < 16; off <<= 1)
#pragma unroll
        for (int r = 0; r < 8; r++)
            rmin[r] = fminf(rmin[r], __shfl_xor_sync(0xffffffffu, rmin[r], off));

    if (tx == 0) {
#pragma unroll
        for (int r = 0; r < 8; r++)
            atomicMin(&g_negmin[i0 + ty * 8 + r], __float_as_uint(rmin[r]));
    }
}

// ---------------- positives: one warp per anchor ----------------
__global__ __launch_bounds__(256)
void pos_kernel(const float* __restrict__ E) {
    int warp = (blockIdx.x * blockDim.x + threadIdx.x) >> 5;
    int lane = threadIdx.x & 31;
    if (warp >= BN) return;
    const int i = warp;

    unsigned nm_bits = g_negmin[i];
    const bool has_neg = (nm_bits != 0x7f800000u);
    const float hn = __uint_as_float(nm_bits);
    const int li = g_lab32[i];
    const float si = g_sq[i];

    const float* ra = E + (size_t)i * DD;
    float a0 = ra[lane], a1 = ra[lane + 32], a2 = ra[lane + 64], a3 = ra[lane + 96];

    float lsum = 0.f;
    int   lcnt = 0;

    for (int jb = 0; jb < BN; jb += 32) {
        int j = jb + lane;
        bool m = (g_lab32[j] == li) && (j != i);
        unsigned bal = __ballot_sync(0xffffffffu, m);
        while (bal) {
            int b = __ffs(bal) - 1;
            bal &= bal - 1;
            int jj = jb + b;
            const float* rb = E + (size_t)jj * DD;
            float p = a0 * rb[lane] + a1 * rb[lane + 32] + a2 * rb[lane + 64] + a3 * rb[lane + 96];
#pragma unroll
            for (int off = 16; off; off >>= 1) p += __shfl_xor_sync(0xffffffffu, p, off);
            float dpos = fmaxf(si + g_sq[jj] - 2.f * p, 0.f);
            if (has_neg && hn < dpos) {
                // relu(dpos - hn + margin): since hn < dpos the argument is > margin > 0
                lsum += dpos - hn + TMARGIN;
                lcnt += 1;
            }
        }
    }
    if (lane == 0 && lcnt) {
        atomicAdd(&g_total, lsum);
        atomicAdd(&g_count, lcnt);
    }
}

// ---------------- finalize ----------------
__global__ void fin_kernel(float* out, int n) {
    float c = (float)g_count;
    float loss = g_total / fmaxf(c, 1.f);
    if (n >= 1) out[0] = loss;
    if (n >= 2) out[1] = c;
}

extern "C" void kernel_launch(void* const* d_in, const int* in_sizes, int n_in,
                              void* d_out, int out_size) {
    const float* E = (const float*)d_in[0];
    const void*  lab = d_in[1];
    float* out = (float*)d_out;

    detect_kernel<<<1, 128>>>((const int*)lab);
    init_kernel<<<(BN + 255) / 256, 256>>>(lab);
    sq_kernel<<<BN / 8, 256>>>(E);          // 8 warps/block, warp per row
    dim3 g(BN / BI, JSPLIT);
    negmine_kernel<<<g, 256>>>(E);
    pos_kernel<<<BN / 8, 256>>>(E);
    fin_kernel<<<1, 1>>>(out, out_size);
}

// round 4
// speedup vs baseline: 1.6925x; 1.6925x over previous
#include <cuda_runtime.h>
#include <cuda_fp16.h>
#include <cstdint>

// ---------------- problem constants ----------------
#define BN 8192
#define DD 128
#define TMARGIN 1.0f

// ---------------- tiling ----------------
#define TI 128
#define TJ 128
#define JSPLIT 2
#define JCH (BN / JSPLIT)      // 4096
#define NT (JCH / TJ)          // 32 j-tiles per CTA
#define KK 256                 // concatenated K: [hi | lo] vs [hi | hi]
#define PITCH 528              // 512B data + 16B pad (conflict-free ldmatrix)
#define TILEB (128 * PITCH)    // 67584 bytes per SMEM tile
#define PCAP (1 << 18)

// ---------------- device globals ----------------
__device__ float        g_sq[BN];
__device__ unsigned int g_negmin[BN];
__device__ float        g_total;
__device__ int          g_count;
__device__ int          g_lab32[BN];
__device__ int          g_is64;
__device__ __half       g_A2[BN * KK];   // [hi(128) | lo(128)] per row
__device__ __half       g_B2[BN * KK];   // [hi(128) | hi(128)] per row
__device__ int          g_pcount;
__device__ int          g_pi[PCAP];
__device__ float        g_pd[PCAP];

// ---------------- PTX helpers (all baseline sm_80-era, legal on sm_103) ----------------
__device__ __forceinline__ uint32_t smem_u32(const void* p) {
    uint32_t a;
    asm("{ .reg .u64 t; cvta.to.shared.u64 t, %1; cvt.u32.u64 %0, t; }" : "=r"(a) : "l"(p));
    return a;
}
#define CP_ASYNC16(dst, src) \
    asm volatile("cp.async.cg.shared.global [%0], [%1], 16;" :: "r"(dst), "l"(src))
#define CP_COMMIT() asm volatile("cp.async.commit_group;")
#define CP_WAIT1()  asm volatile("cp.async.wait_group 1;")
#define CP_WAIT0()  asm volatile("cp.async.wait_group 0;")

#define LDSM_X4(r0, r1, r2, r3, addr) \
    asm volatile("ldmatrix.sync.aligned.m8n8.x4.shared.b16 {%0,%1,%2,%3}, [%4];" \
                 : "=r"(r0), "=r"(r1), "=r"(r2), "=r"(r3) : "r"(addr))
#define LDSM_X2(r0, r1, addr) \
    asm volatile("ldmatrix.sync.aligned.m8n8.x2.shared.b16 {%0,%1}, [%2];" \
                 : "=r"(r0), "=r"(r1) : "r"(addr))

#define MMA16816(d, a, b) \
    asm volatile("mma.sync.aligned.m16n8k16.row.col.f32.f16.f16.f32 " \
                 "{%0,%1,%2,%3}, {%4,%5,%6,%7}, {%8,%9}, {%0,%1,%2,%3};" \
                 : "+f"((d)[0]), "+f"((d)[1]), "+f"((d)[2]), "+f"((d)[3]) \
                 : "r"((a)[0]), "r"((a)[1]), "r"((a)[2]), "r"((a)[3]), \
                   "r"((b)[0]), "r"((b)[1]))

// ---------------- SMEM layout ----------------
#define OFF_A    0
#define OFF_B    TILEB                 // 2 buffers: OFF_B + buf*TILEB
#define OFF_SQJ  (3 * TILEB)           // float [2][128]
#define OFF_LABJ (OFF_SQJ + 1024)      // int   [2][128]
#define OFF_SMIN (OFF_LABJ + 1024)     // uint  [128]
#define SMEM_TOTAL (OFF_SMIN + 512)

// ---------------- small kernels ----------------
__global__ void detect_kernel(const int* __restrict__ raw) {
    __shared__ int s_any;
    if (threadIdx.x == 0) s_any = 0;
    __syncthreads();
    int v = raw[2 * threadIdx.x + 1];
    unsigned any = __ballot_sync(0xffffffffu, v != 0);
    if ((threadIdx.x & 31) == 0 && any) atomicOr(&s_any, 1);
    __syncthreads();
    if (threadIdx.x == 0) g_is64 = (s_any == 0) ? 1 : 0;
}

__global__ void init_kernel(const void* __restrict__ labraw) {
    int i = blockIdx.x * blockDim.x + threadIdx.x;
    if (i < BN) {
        g_negmin[i] = 0x7f800000u;
        g_lab32[i] = g_is64 ? (int)((const long long*)labraw)[i] : ((const int*)labraw)[i];
    }
    if (i == 0) { g_total = 0.f; g_count = 0; g_pcount = 0; }
}

__global__ void cvt_kernel(const float* __restrict__ E) {
    int idx = blockIdx.x * blockDim.x + threadIdx.x;   // over BN*DD
    int row = idx >> 7, k = idx & 127;
    float v = E[idx];
    __half hi = __float2half(v);
    __half lo = __float2half(v - __half2float(hi));
    g_A2[(size_t)row * KK + k]       = hi;
    g_A2[(size_t)row * KK + 128 + k] = lo;
    g_B2[(size_t)row * KK + k]       = hi;
    g_B2[(size_t)row * KK + 128 + k] = hi;
}

__global__ void sq_kernel(const float* __restrict__ E) {
    int warp = (blockIdx.x * blockDim.x + threadIdx.x) >> 5;
    int lane = threadIdx.x & 31;
    if (warp >= BN) return;
    const float* row = E + (size_t)warp * DD;
    float v0 = row[lane], v1 = row[lane + 32], v2 = row[lane + 64], v3 = row[lane + 96];
    float s = v0 * v0 + v1 * v1 + v2 * v2 + v3 * v3;
#pragma unroll
    for (int off = 16; off; off >>= 1) s += __shfl_xor_sync(0xffffffffu, s, off);
    if (lane == 0) g_sq[warp] = s;
}

// ---------------- HMMA fused Gram + masked-min + positive emission ----------------
__global__ __launch_bounds__(256, 1) void negmine_kernel() {
    extern __shared__ char smem[];
    const uint32_t sb = smem_u32(smem);
    const int tid = threadIdx.x;
    const int w = tid >> 5, lane = tid & 31;
    const int g = lane >> 2, t = lane & 3;
    const int i0 = blockIdx.x * TI;
    const int jbase = blockIdx.y * JCH;

    const int mrow0 = (w & 1) * 64;     // warp m-offset
    const int ncol0 = (w >> 1) * 32;    // warp n-offset

    float* sqj_all  = reinterpret_cast<float*>(smem + OFF_SQJ);
    int*   labj_all = reinterpret_cast<int*>(smem + OFF_LABJ);
    unsigned* smin  = reinterpret_cast<unsigned*>(smem + OFF_SMIN);

    // ---- prologue: A tile + B tile 0 via cp.async ----
#pragma unroll
    for (int c = tid; c < 4096; c += 256) {
        int row = c >> 5, col = c & 31;
        CP_ASYNC16(sb + OFF_A + row * PITCH + col * 16,
                   (const void*)(g_A2 + (size_t)(i0 + row) * KK + col * 8));
    }
#pragma unroll
    for (int c = tid; c < 4096; c += 256) {
        int row = c >> 5, col = c & 31;
        CP_ASYNC16(sb + OFF_B + row * PITCH + col * 16,
                   (const void*)(g_B2 + (size_t)(jbase + row) * KK + col * 8));
    }
    CP_COMMIT();
    if (tid < 128) {
        sqj_all[tid]  = g_sq[jbase + tid];
        labj_all[tid] = g_lab32[jbase + tid];
        smin[tid] = 0x7f800000u;
    }

    // ---- per-lane ldmatrix base offsets ----
    // A frag x4: lane L -> matrix L>>3; row = (L&7) + ((L>>3)&1)*8 ; kbyte = (L>>4)*16
    uint32_t abase[4];
#pragma unroll
    for (int mf = 0; mf < 4; mf++)
        abase[mf] = sb + OFF_A + (uint32_t)((mrow0 + mf * 16 + ((lane >> 3) & 1) * 8 + (lane & 7)) * PITCH)
                    + (uint32_t)((lane >> 4) * 16);
    // B frag x2: lanes 0-15: row = (L&7); kbyte = ((L>>3)&1)*16
    uint32_t bbase[4];
#pragma unroll
    for (int nf = 0; nf < 4; nf++)
        bbase[nf] = sb + OFF_B + (uint32_t)((ncol0 + nf * 8 + (lane & 7)) * PITCH)
                    + (uint32_t)(((lane >> 3) & 1) * 16);

    // ---- epilogue row constants ----
    float si[8]; int li[8]; int ig[8];
#pragma unroll
    for (int mf = 0; mf < 4; mf++)
#pragma unroll
        for (int hh = 0; hh < 2; hh++) {
            int r = mrow0 + mf * 16 + g + hh * 8;
            si[mf * 2 + hh] = g_sq[i0 + r];
            li[mf * 2 + hh] = g_lab32[i0 + r];
            ig[mf * 2 + hh] = i0 + r;
        }
    float rmin[8];
#pragma unroll
    for (int h = 0; h < 8; h++) rmin[h] = __int_as_float(0x7f800000);

    // ---- main loop over j-tiles ----
    for (int jt = 0; jt < NT; jt++) {
        const int b0 = jt & 1;
        // [1] prefetch next tile
        if (jt + 1 < NT) {
            const int b1 = (jt + 1) & 1;
            const int j1 = jbase + (jt + 1) * TJ;
#pragma unroll
            for (int c = tid; c < 4096; c += 256) {
                int row = c >> 5, col = c & 31;
                CP_ASYNC16(sb + OFF_B + b1 * TILEB + row * PITCH + col * 16,
                           (const void*)(g_B2 + (size_t)(j1 + row) * KK + col * 8));
            }
            CP_COMMIT();
            if (tid < 128) {
                sqj_all[b1 * 128 + tid]  = g_sq[j1 + tid];
                labj_all[b1 * 128 + tid] = g_lab32[j1 + tid];
            }
            CP_WAIT1();
        } else {
            CP_WAIT0();
        }
        __syncthreads();

        // [2] compute: 16 k-steps of m16n8k16 over K=256
        float acc[4][4][4];
#pragma unroll
        for (int mf = 0; mf < 4; mf++)
#pragma unroll
            for (int nf = 0; nf < 4; nf++)
#pragma unroll
                for (int e = 0; e < 4; e++) acc[mf][nf][e] = 0.f;

        const uint32_t bufoff = (uint32_t)(b0 * TILEB);
#pragma unroll
        for (int ks = 0; ks < KK / 16; ks++) {
            uint32_t a[4][4];
#pragma unroll
            for (int mf = 0; mf < 4; mf++)
                LDSM_X4(a[mf][0], a[mf][1], a[mf][2], a[mf][3], abase[mf] + ks * 32);
            uint32_t bf[4][2];
#pragma unroll
            for (int nf = 0; nf < 4; nf++)
                LDSM_X2(bf[nf][0], bf[nf][1], bbase[nf] + bufoff + ks * 32);
#pragma unroll
            for (int mf = 0; mf < 4; mf++)
#pragma unroll
                for (int nf = 0; nf < 4; nf++)
                    MMA16816(acc[mf][nf], a[mf], bf[nf]);
        }

        // [3] epilogue: distance + relu + masked min + positive emission
        const float* sqj  = sqj_all + b0 * 128;
        const int*   labj = labj_all + b0 * 128;
        const int j0 = jbase + jt * TJ;
#pragma unroll
        for (int nf = 0; nf < 4; nf++) {
            const int c0 = ncol0 + nf * 8 + 2 * t;
            const float q0 = sqj[c0], q1 = sqj[c0 + 1];
            const int lb0 = labj[c0], lb1 = labj[c0 + 1];
#pragma unroll
            for (int mf = 0; mf < 4; mf++)
#pragma unroll
                for (int hh = 0; hh < 2; hh++) {
                    const int ri = mf * 2 + hh;
                    float dd0 = fmaxf(si[ri] + q0 - 2.0f * acc[mf][nf][hh * 2 + 0], 0.f);
                    float dd1 = fmaxf(si[ri] + q1 - 2.0f * acc[mf][nf][hh * 2 + 1], 0.f);
                    if (lb0 != li[ri]) rmin[ri] = fminf(rmin[ri], dd0);
                    else if (j0 + c0 != ig[ri]) {
                        int slot = atomicAdd(&g_pcount, 1);
                        if (slot < PCAP) { g_pi[slot] = ig[ri]; g_pd[slot] = dd0; }
                    }
                    if (lb1 != li[ri]) rmin[ri] = fminf(rmin[ri], dd1);
                    else if (j0 + c0 + 1 != ig[ri]) {
                        int slot = atomicAdd(&g_pcount, 1);
                        if (slot < PCAP) { g_pi[slot] = ig[ri]; g_pd[slot] = dd1; }
                    }
                }
        }
        __syncthreads();   // protect buffer b0 before it is re-filled at jt+2
    }

    // ---- final min reduction ----
#pragma unroll
    for (int h = 0; h < 8; h++) {
        rmin[h] = fminf(rmin[h], __shfl_xor_sync(0xffffffffu, rmin[h], 1));
        rmin[h] = fminf(rmin[h], __shfl_xor_sync(0xffffffffu, rmin[h], 2));
    }
    if (t == 0) {
#pragma unroll
        for (int mf = 0; mf < 4; mf++)
#pragma unroll
            for (int hh = 0; hh < 2; hh++) {
                int rloc = mrow0 + mf * 16 + g + hh * 8;
                atomicMin(&smin[rloc], __float_as_uint(rmin[mf * 2 + hh]));
            }
    }
    __syncthreads();
    if (tid < 128) atomicMin(&g_negmin[i0 + tid], smin[tid]);
}

// ---------------- positives finish ----------------
__global__ void pos_finish_kernel() {
    int idx = blockIdx.x * blockDim.x + threadIdx.x;
    int n = min(g_pcount, PCAP);
    if (idx >= n) return;
    int i = g_pi[idx];
    unsigned nb = g_negmin[i];
    if (nb == 0x7f800000u) return;
    float hn = __uint_as_float(nb);
    float dpos = g_pd[idx];
    if (hn < dpos) {
        atomicAdd(&g_total, dpos - hn + TMARGIN);
        atomicAdd(&g_count, 1);
    }
}

__global__ void fin_kernel(float* out, int n) {
    float c = (float)g_count;
    float loss = g_total / fmaxf(c, 1.f);
    if (n >= 1) out[0] = loss;
    if (n >= 2) out[1] = c;
}

extern "C" void kernel_launch(void* const* d_in, const int* in_sizes, int n_in,
                              void* d_out, int out_size) {
    const float* E = (const float*)d_in[0];
    const void* lab = d_in[1];
    float* out = (float*)d_out;

    cudaFuncSetAttribute(negmine_kernel, cudaFuncAttributeMaxDynamicSharedMemorySize, SMEM_TOTAL);

    detect_kernel<<<1, 128>>>((const int*)lab);
    init_kernel<<<(BN + 255) / 256, 256>>>(lab);
    cvt_kernel<<<(BN * DD) / 256, 256>>>(E);
    sq_kernel<<<BN / 8, 256>>>(E);
    dim3 g(BN / TI, JSPLIT);
    negmine_kernel<<<g, 256, SMEM_TOTAL>>>();
    pos_finish_kernel<<<PCAP / 256, 256>>>();
    fin_kernel<<<1, 1>>>(out, out_size);
}

// round 5
// speedup vs baseline: 2.2972x; 1.3573x over previous
#include <cuda_runtime.h>
#include <cuda_fp16.h>
#include <cstdint>

// ---------------- problem constants ----------------
#define BN 8192
#define DD 128
#define TMARGIN 1.0f

// ---------------- tiling ----------------
#define TI 128
#define TJ 128
#define JSPLIT 2
#define JCH (BN / JSPLIT)      // 4096
#define NT (JCH / TJ)          // 32 j-tiles per CTA
#define PITCH 272              // 256B data + 16B pad (odd 16B-units -> conflict-free ldmatrix)
#define TILEB (128 * PITCH)    // 34816 bytes
#define PCAP (1 << 18)
#define NTHREADS 512

// ---------------- device globals ----------------
__device__ float        g_sq[BN];
__device__ unsigned int g_negmin[BN];
__device__ float        g_total;
__device__ int          g_count;
__device__ int          g_lab32[BN];
__device__ int          g_is64;
__device__ __half       g_H[BN * DD];   // fp16(hi) of embeddings
__device__ int          g_pcount;
__device__ int          g_pi[PCAP];
__device__ float        g_pd[PCAP];

// ---------------- PTX helpers (baseline, legal at target sm_103) ----------------
__device__ __forceinline__ uint32_t smem_u32(const void* p) {
    uint32_t a;
    asm("{ .reg .u64 t; cvta.to.shared.u64 t, %1; cvt.u32.u64 %0, t; }" : "=r"(a) : "l"(p));
    return a;
}
#define CP_ASYNC16(dst, src) \
    asm volatile("cp.async.cg.shared.global [%0], [%1], 16;" :: "r"(dst), "l"(src))
#define CP_COMMIT() asm volatile("cp.async.commit_group;")
#define CP_WAIT1()  asm volatile("cp.async.wait_group 1;")
#define CP_WAIT0()  asm volatile("cp.async.wait_group 0;")

#define LDSM_X4(r0, r1, r2, r3, addr) \
    asm volatile("ldmatrix.sync.aligned.m8n8.x4.shared.b16 {%0,%1,%2,%3}, [%4];" \
                 : "=r"(r0), "=r"(r1), "=r"(r2), "=r"(r3) : "r"(addr))

#define MMA16816(d, a, b0, b1) \
    asm volatile("mma.sync.aligned.m16n8k16.row.col.f32.f16.f16.f32 " \
                 "{%0,%1,%2,%3}, {%4,%5,%6,%7}, {%8,%9}, {%0,%1,%2,%3};" \
                 : "+f"((d)[0]), "+f"((d)[1]), "+f"((d)[2]), "+f"((d)[3]) \
                 : "r"((a)[0]), "r"((a)[1]), "r"((a)[2]), "r"((a)[3]), \
                   "r"(b0), "r"(b1))

// ---------------- SMEM layout ----------------
#define OFF_A    0
#define OFF_B    TILEB                 // 2 buffers: OFF_B + buf*TILEB
#define OFF_SQJ  (3 * TILEB)           // float [2][128]
#define OFF_LABJ (OFF_SQJ + 1024)      // int   [2][128]
#define OFF_SMIN (OFF_LABJ + 1024)     // uint  [128]
#define SMEM_TOTAL (OFF_SMIN + 512)

// ---------------- small kernels ----------------
__global__ void detect_kernel(const int* __restrict__ raw) {
    __shared__ int s_any;
    if (threadIdx.x == 0) s_any = 0;
    __syncthreads();
    int v = raw[2 * threadIdx.x + 1];
    unsigned any = __ballot_sync(0xffffffffu, v != 0);
    if ((threadIdx.x & 31) == 0 && any) atomicOr(&s_any, 1);
    __syncthreads();
    if (threadIdx.x == 0) g_is64 = (s_any == 0) ? 1 : 0;
}

__global__ void init_kernel(const void* __restrict__ labraw) {
    int i = blockIdx.x * blockDim.x + threadIdx.x;
    if (i < BN) {
        g_negmin[i] = 0x7f800000u;
        g_lab32[i] = g_is64 ? (int)((const long long*)labraw)[i] : ((const int*)labraw)[i];
    }
    if (i == 0) { g_total = 0.f; g_count = 0; g_pcount = 0; }
}

// fused: fp32 -> fp16 convert + row squared-norm (one warp per row)
__global__ void prep_kernel(const float* __restrict__ E) {
    int warp = (blockIdx.x * blockDim.x + threadIdx.x) >> 5;
    int lane = threadIdx.x & 31;
    if (warp >= BN) return;
    const float* row = E + (size_t)warp * DD;
    __half* hrow = g_H + (size_t)warp * DD;
    float s = 0.f;
#pragma unroll
    for (int q = 0; q < 4; q++) {
        float v = row[lane + 32 * q];
        hrow[lane + 32 * q] = __float2half(v);
        s += v * v;
    }
#pragma unroll
    for (int off = 16; off; off >>= 1) s += __shfl_xor_sync(0xffffffffu, s, off);
    if (lane == 0) g_sq[warp] = s;
}

// ---------------- HMMA fused Gram + masked-min + positive emission ----------------
// 512 threads: warp w -> m-rows (w&3)*32 + [0,32), n-cols (w>>2)*32 + [0,32)
__global__ __launch_bounds__(NTHREADS, 1) void negmine_kernel() {
    extern __shared__ char smem[];
    const uint32_t sb = smem_u32(smem);
    const int tid = threadIdx.x;
    const int w = tid >> 5, lane = tid & 31;
    const int g = lane >> 2, t = lane & 3;
    const int i0 = blockIdx.x * TI;
    const int jbase = blockIdx.y * JCH;

    const int mrow0 = (w & 3) * 32;
    const int ncol0 = (w >> 2) * 32;

    float* sqj_all  = reinterpret_cast<float*>(smem + OFF_SQJ);
    int*   labj_all = reinterpret_cast<int*>(smem + OFF_LABJ);
    unsigned* smin  = reinterpret_cast<unsigned*>(smem + OFF_SMIN);

    // ---- prologue: A tile + B tile 0 via cp.async (2048 x 16B chunks each) ----
#pragma unroll
    for (int c = tid; c < 2048; c += NTHREADS) {
        int row = c >> 4, col = c & 15;
        CP_ASYNC16(sb + OFF_A + row * PITCH + col * 16,
                   (const void*)(g_H + (size_t)(i0 + row) * DD + col * 8));
    }
#pragma unroll
    for (int c = tid; c < 2048; c += NTHREADS) {
        int row = c >> 4, col = c & 15;
        CP_ASYNC16(sb + OFF_B + row * PITCH + col * 16,
                   (const void*)(g_H + (size_t)(jbase + row) * DD + col * 8));
    }
    CP_COMMIT();
    if (tid < 128) {
        sqj_all[tid]  = g_sq[jbase + tid];
        labj_all[tid] = g_lab32[jbase + tid];
        smin[tid] = 0x7f800000u;
    }

    // ---- per-lane ldmatrix base offsets ----
    uint32_t abase[2];
#pragma unroll
    for (int mf = 0; mf < 2; mf++)
        abase[mf] = sb + OFF_A
                  + (uint32_t)((mrow0 + mf * 16 + ((lane >> 3) & 1) * 8 + (lane & 7)) * PITCH)
                  + (uint32_t)((lane >> 4) * 16);
    // B x4 pair p covers n8 frags {2p, 2p+1}:
    // lanes 0-7 -> nblock p, k0 ; 8-15 -> p, k8 ; 16-23 -> p+8rows, k0 ; 24-31 -> +8, k8
    uint32_t bbase[2];
#pragma unroll
    for (int p = 0; p < 2; p++)
        bbase[p] = sb + OFF_B
                 + (uint32_t)((ncol0 + p * 16 + ((lane >> 4) & 1) * 8 + (lane & 7)) * PITCH)
                 + (uint32_t)(((lane >> 3) & 1) * 16);

    // ---- epilogue row constants ----
    float si[4]; int li[4]; int ig[4];
#pragma unroll
    for (int mf = 0; mf < 2; mf++)
#pragma unroll
        for (int hh = 0; hh < 2; hh++) {
            int r = mrow0 + mf * 16 + hh * 8 + g;
            si[mf * 2 + hh] = g_sq[i0 + r];
            li[mf * 2 + hh] = g_lab32[i0 + r];
            ig[mf * 2 + hh] = i0 + r;
        }
    float rmin[4];
#pragma unroll
    for (int h = 0; h < 4; h++) rmin[h] = __int_as_float(0x7f800000);

    // ---- main loop over j-tiles ----
    for (int jt = 0; jt < NT; jt++) {
        const int b0 = jt & 1;
        if (jt + 1 < NT) {
            const int b1 = (jt + 1) & 1;
            const int j1 = jbase + (jt + 1) * TJ;
#pragma unroll
            for (int c = tid; c < 2048; c += NTHREADS) {
                int row = c >> 4, col = c & 15;
                CP_ASYNC16(sb + OFF_B + b1 * TILEB + row * PITCH + col * 16,
                           (const void*)(g_H + (size_t)(j1 + row) * DD + col * 8));
            }
            CP_COMMIT();
            if (tid < 128) {
                sqj_all[b1 * 128 + tid]  = g_sq[j1 + tid];
                labj_all[b1 * 128 + tid] = g_lab32[j1 + tid];
            }
            CP_WAIT1();
        } else {
            CP_WAIT0();
        }
        __syncthreads();

        // [2] compute: 8 k-steps of m16n8k16 over K=128
        float acc[2][4][4];
#pragma unroll
        for (int mf = 0; mf < 2; mf++)
#pragma unroll
            for (int nf = 0; nf < 4; nf++)
#pragma unroll
                for (int e = 0; e < 4; e++) acc[mf][nf][e] = 0.f;

        const uint32_t bufoff = (uint32_t)(b0 * TILEB);
#pragma unroll
        for (int ks = 0; ks < DD / 16; ks++) {
            uint32_t a[2][4];
#pragma unroll
            for (int mf = 0; mf < 2; mf++)
                LDSM_X4(a[mf][0], a[mf][1], a[mf][2], a[mf][3], abase[mf] + ks * 32);
            uint32_t bf[2][4];
#pragma unroll
            for (int p = 0; p < 2; p++)
                LDSM_X4(bf[p][0], bf[p][1], bf[p][2], bf[p][3], bbase[p] + bufoff + ks * 32);
#pragma unroll
            for (int mf = 0; mf < 2; mf++)
#pragma unroll
                for (int nf = 0; nf < 4; nf++)
                    MMA16816(acc[mf][nf], a[mf], bf[nf >> 1][(nf & 1) * 2], bf[nf >> 1][(nf & 1) * 2 + 1]);
        }

        // [3] epilogue: distance + relu + masked min + positive emission
        const float* sqj  = sqj_all + b0 * 128;
        const int*   labj = labj_all + b0 * 128;
        const int j0 = jbase + jt * TJ;
#pragma unroll
        for (int nf = 0; nf < 4; nf++) {
            const int c0 = ncol0 + nf * 8 + 2 * t;
            const float q0 = sqj[c0], q1 = sqj[c0 + 1];
            const int lb0 = labj[c0], lb1 = labj[c0 + 1];
#pragma unroll
            for (int mf = 0; mf < 2; mf++)
#pragma unroll
                for (int hh = 0; hh < 2; hh++) {
                    const int ri = mf * 2 + hh;
                    float dd0 = fmaxf(si[ri] + q0 - 2.0f * acc[mf][nf][hh * 2 + 0], 0.f);
                    float dd1 = fmaxf(si[ri] + q1 - 2.0f * acc[mf][nf][hh * 2 + 1], 0.f);
                    if (lb0 != li[ri]) rmin[ri] = fminf(rmin[ri], dd0);
                    else if (j0 + c0 != ig[ri]) {
                        int slot = atomicAdd(&g_pcount, 1);
                        if (slot < PCAP) { g_pi[slot] = ig[ri]; g_pd[slot] = dd0; }
                    }
                    if (lb1 != li[ri]) rmin[ri] = fminf(rmin[ri], dd1);
                    else if (j0 + c0 + 1 != ig[ri]) {
                        int slot = atomicAdd(&g_pcount, 1);
                        if (slot < PCAP) { g_pi[slot] = ig[ri]; g_pd[slot] = dd1; }
                    }
                }
        }
        __syncthreads();   // protect buffer b0 before refill at jt+2
    }

    // ---- final min reduction ----
#pragma unroll
    for (int h = 0; h < 4; h++) {
        rmin[h] = fminf(rmin[h], __shfl_xor_sync(0xffffffffu, rmin[h], 1));
        rmin[h] = fminf(rmin[h], __shfl_xor_sync(0xffffffffu, rmin[h], 2));
    }
    if (t == 0) {
#pragma unroll
        for (int mf = 0; mf < 2; mf++)
#pragma unroll
            for (int hh = 0; hh < 2; hh++) {
                int rloc = mrow0 + mf * 16 + hh * 8 + g;
                atomicMin(&smin[rloc], __float_as_uint(rmin[mf * 2 + hh]));
            }
    }
    __syncthreads();
    if (tid < 128) atomicMin(&g_negmin[i0 + tid], smin[tid]);
}

// ---------------- positives finish ----------------
__global__ void pos_finish_kernel() {
    int idx = blockIdx.x * blockDim.x + threadIdx.x;
    int n = min(g_pcount, PCAP);
    if (idx >= n) return;
    int i = g_pi[idx];
    unsigned nb = g_negmin[i];
    if (nb == 0x7f800000u) return;
    float hn = __uint_as_float(nb);
    float dpos = g_pd[idx];
    if (hn < dpos) {
        atomicAdd(&g_total, dpos - hn + TMARGIN);
        atomicAdd(&g_count, 1);
    }
}

__global__ void fin_kernel(float* out, int n) {
    float c = (float)g_count;
    float loss = g_total / fmaxf(c, 1.f);
    if (n >= 1) out[0] = loss;
    if (n >= 2) out[1] = c;
}

extern "C" void kernel_launch(void* const* d_in, const int* in_sizes, int n_in,
                              void* d_out, int out_size) {
    const float* E = (const float*)d_in[0];
    const void* lab = d_in[1];
    float* out = (float*)d_out;

    cudaFuncSetAttribute(negmine_kernel, cudaFuncAttributeMaxDynamicSharedMemorySize, SMEM_TOTAL);

    detect_kernel<<<1, 128>>>((const int*)lab);
    init_kernel<<<(BN + 255) / 256, 256>>>(lab);
    prep_kernel<<<BN / 8, 256>>>(E);
    dim3 g(BN / TI, JSPLIT);
    negmine_kernel<<<g, NTHREADS, SMEM_TOTAL>>>();
    pos_finish_kernel<<<PCAP / 256, 256>>>();
    fin_kernel<<<1, 1>>>(out, out_size);
}

// round 7
// speedup vs baseline: 4.6742x; 2.0347x over previous
#include <cuda_runtime.h>
#include <cuda_fp16.h>
#include <cstdint>

// ---------------- problem constants ----------------
#define BN 8192
#define DD 128
#define TMARGIN 1.0f

// ---------------- tiling ----------------
#define TI 128
#define TJ 64                  // CTA tile: 128 x 64 (16 warps x 32x16)
#define JSPLIT 4
#define JCH (BN / JSPLIT)      // 2048
#define NT (JCH / TJ)          // 32 j-tiles per CTA
#define PITCH 272              // 256B data + 16B pad -> conflict-free ldmatrix
#define ATILEB (128 * PITCH)   // 34816
#define BTILEB (TJ * PITCH)    // 17408
#define PCAP (1 << 18)
#define NTHREADS 512

// ---------------- device globals ----------------
__device__ float        g_sq[BN];
__device__ unsigned int g_negmin[BN];
__device__ float        g_total;
__device__ int          g_count;
__device__ int          g_lab32[BN];
__device__ int          g_is64;
__device__ __half       g_H[BN * DD];   // fp16 of embeddings
__device__ int          g_pcount;
__device__ int          g_pi[PCAP];
__device__ float        g_pd[PCAP];

// ---------------- PTX helpers (baseline, legal at target sm_103) ----------------
__device__ __forceinline__ uint32_t smem_u32(const void* p) {
    uint32_t a;
    asm("{ .reg .u64 t; cvta.to.shared.u64 t, %1; cvt.u32.u64 %0, t; }" : "=r"(a) : "l"(p));
    return a;
}
#define CP_ASYNC16(dst, src) \
    asm volatile("cp.async.cg.shared.global [%0], [%1], 16;" :: "r"(dst), "l"(src))
#define CP_COMMIT() asm volatile("cp.async.commit_group;")
#define CP_WAIT1()  asm volatile("cp.async.wait_group 1;")
#define CP_WAIT0()  asm volatile("cp.async.wait_group 0;")

#define LDSM_X4(r0, r1, r2, r3, addr) \
    asm volatile("ldmatrix.sync.aligned.m8n8.x4.shared.b16 {%0,%1,%2,%3}, [%4];" \
                 : "=r"(r0), "=r"(r1), "=r"(r2), "=r"(r3) : "r"(addr))

#define MMA16816(d, a0, a1, a2, a3, b0, b1) \
    asm volatile("mma.sync.aligned.m16n8k16.row.col.f32.f16.f16.f32 " \
                 "{%0,%1,%2,%3}, {%4,%5,%6,%7}, {%8,%9}, {%0,%1,%2,%3};" \
                 : "+f"((d)[0]), "+f"((d)[1]), "+f"((d)[2]), "+f"((d)[3]) \
                 : "r"(a0), "r"(a1), "r"(a2), "r"(a3), "r"(b0), "r"(b1))

// ---------------- SMEM layout ----------------
#define OFF_A    0
#define OFF_B    ATILEB                      // 2 buffers of BTILEB
#define OFF_SQJ  (ATILEB + 2 * BTILEB)       // float [2][TJ]
#define OFF_LABJ (OFF_SQJ + 2 * TJ * 4)      // int   [2][TJ]
#define OFF_SMIN (OFF_LABJ + 2 * TJ * 4)     // uint  [128]
#define SMEM_TOTAL (OFF_SMIN + 512)          // ~71.2 KB -> 2 CTAs/SM

// ---------------- small kernels ----------------
__global__ void detect_kernel(const int* __restrict__ raw) {
    __shared__ int s_any;
    if (threadIdx.x == 0) s_any = 0;
    __syncthreads();
    int v = raw[2 * threadIdx.x + 1];
    unsigned any = __ballot_sync(0xffffffffu, v != 0);
    if ((threadIdx.x & 31) == 0 && any) atomicOr(&s_any, 1);
    __syncthreads();
    if (threadIdx.x == 0) g_is64 = (s_any == 0) ? 1 : 0;
}

__global__ void init_kernel(const void* __restrict__ labraw) {
    int i = blockIdx.x * blockDim.x + threadIdx.x;
    if (i < BN) {
        g_negmin[i] = 0x7f800000u;
        g_lab32[i] = g_is64 ? (int)((const long long*)labraw)[i] : ((const int*)labraw)[i];
    }
    if (i == 0) { g_total = 0.f; g_count = 0; g_pcount = 0; }
}

__global__ void prep_kernel(const float* __restrict__ E) {
    int warp = (blockIdx.x * blockDim.x + threadIdx.x) >> 5;
    int lane = threadIdx.x & 31;
    if (warp >= BN) return;
    const float* row = E + (size_t)warp * DD;
    __half* hrow = g_H + (size_t)warp * DD;
    float s = 0.f;
#pragma unroll
    for (int q = 0; q < 4; q++) {
        float v = row[lane + 32 * q];
        hrow[lane + 32 * q] = __float2half(v);
        s += v * v;
    }
#pragma unroll
    for (int off = 16; off; off >>= 1) s += __shfl_xor_sync(0xffffffffu, s, off);
    if (lane == 0) g_sq[warp] = s;
}

// ---------------- HMMA fused Gram + masked-min + positive emission ----------------
// 512 threads, 2 CTAs/SM. Warp w: m-rows (w&3)*32+[0,32), n-cols (w>>2)*16+[0,16).
// CTA tile 128 (m) x 64 (n): 16 warps cover it exactly.
__global__ __launch_bounds__(NTHREADS, 2) void negmine_kernel() {
    extern __shared__ char smem[];
    const uint32_t sb = smem_u32(smem);
    const int tid = threadIdx.x;
    const int w = tid >> 5, lane = tid & 31;
    const int g = lane >> 2, t = lane & 3;
    const int i0 = blockIdx.x * TI;
    const int jbase = blockIdx.y * JCH;

    const int mrow0 = (w & 3) * 32;
    const int ncol0 = (w >> 2) * 16;

    float* sqj_all  = reinterpret_cast<float*>(smem + OFF_SQJ);
    int*   labj_all = reinterpret_cast<int*>(smem + OFF_LABJ);
    unsigned* smin  = reinterpret_cast<unsigned*>(smem + OFF_SMIN);

    // ---- prologue: A tile (128 rows) + B tile 0 (64 rows) via cp.async ----
#pragma unroll
    for (int c = tid; c < 2048; c += NTHREADS) {
        int row = c >> 4, col = c & 15;
        CP_ASYNC16(sb + OFF_A + row * PITCH + col * 16,
                   (const void*)(g_H + (size_t)(i0 + row) * DD + col * 8));
    }
    {
        int c = tid;                       // 1024 chunks, 512 threads -> 2 each
#pragma unroll
        for (int q = 0; q < 2; q++, c += NTHREADS) {
            int row = c >> 4, col = c & 15;
            CP_ASYNC16(sb + OFF_B + row * PITCH + col * 16,
                       (const void*)(g_H + (size_t)(jbase + row) * DD + col * 8));
        }
    }
    CP_COMMIT();
    if (tid < TJ) {
        sqj_all[tid]  = g_sq[jbase + tid];
        labj_all[tid] = g_lab32[jbase + tid];
    }
    if (tid < 128) smin[tid] = 0x7f800000u;

    // ---- per-lane ldmatrix base offsets ----
    uint32_t abase[2];
#pragma unroll
    for (int mf = 0; mf < 2; mf++)
        abase[mf] = sb + OFF_A
                  + (uint32_t)((mrow0 + mf * 16 + ((lane >> 3) & 1) * 8 + (lane & 7)) * PITCH)
                  + (uint32_t)((lane >> 4) * 16);
    // B x4 covers both n8 frags of the 16-col block:
    // lanes 0-7: frag0 k0 ; 8-15: frag0 k8 ; 16-23: frag1 k0 ; 24-31: frag1 k8
    const uint32_t bbase = sb + OFF_B
                 + (uint32_t)((ncol0 + ((lane >> 4) & 1) * 8 + (lane & 7)) * PITCH)
                 + (uint32_t)(((lane >> 3) & 1) * 16);

    // ---- epilogue row constants (4 rows per thread) ----
    float si[4]; int li[4];
#pragma unroll
    for (int mf = 0; mf < 2; mf++)
#pragma unroll
        for (int hh = 0; hh < 2; hh++) {
            int r = mrow0 + mf * 16 + hh * 8 + g;
            si[mf * 2 + hh] = g_sq[i0 + r];
            li[mf * 2 + hh] = g_lab32[i0 + r];
        }
    float rmin[4];
#pragma unroll
    for (int h = 0; h < 4; h++) rmin[h] = __int_as_float(0x7f800000);

    // ---- main loop over j-tiles ----
    for (int jt = 0; jt < NT; jt++) {
        const int b0 = jt & 1;
        if (jt + 1 < NT) {
            const int b1 = (jt + 1) & 1;
            const int j1 = jbase + (jt + 1) * TJ;
            int c = tid;
#pragma unroll
            for (int q = 0; q < 2; q++, c += NTHREADS) {
                int row = c >> 4, col = c & 15;
                CP_ASYNC16(sb + OFF_B + b1 * BTILEB + row * PITCH + col * 16,
                           (const void*)(g_H + (size_t)(j1 + row) * DD + col * 8));
            }
            CP_COMMIT();
            if (tid < TJ) {
                sqj_all[b1 * TJ + tid]  = g_sq[j1 + tid];
                labj_all[b1 * TJ + tid] = g_lab32[j1 + tid];
            }
            CP_WAIT1();
        } else {
            CP_WAIT0();
        }
        __syncthreads();

        // [2] compute: 8 k-steps, 4 MMA each
        float acc[2][2][4];
#pragma unroll
        for (int mf = 0; mf < 2; mf++)
#pragma unroll
            for (int nf = 0; nf < 2; nf++)
#pragma unroll
                for (int e = 0; e < 4; e++) acc[mf][nf][e] = 0.f;

        const uint32_t bufoff = (uint32_t)(b0 * BTILEB);
#pragma unroll
        for (int ks = 0; ks < DD / 16; ks++) {
            uint32_t a0[4], a1[4], bf[4];
            LDSM_X4(a0[0], a0[1], a0[2], a0[3], abase[0] + ks * 32);
            LDSM_X4(a1[0], a1[1], a1[2], a1[3], abase[1] + ks * 32);
            LDSM_X4(bf[0], bf[1], bf[2], bf[3], bbase + bufoff + ks * 32);
            MMA16816(acc[0][0], a0[0], a0[1], a0[2], a0[3], bf[0], bf[1]);
            MMA16816(acc[0][1], a0[0], a0[1], a0[2], a0[3], bf[2], bf[3]);
            MMA16816(acc[1][0], a1[0], a1[1], a1[2], a1[3], bf[0], bf[1]);
            MMA16816(acc[1][1], a1[0], a1[1], a1[2], a1[3], bf[2], bf[3]);
        }

        // [3] epilogue
        const float* sqj  = sqj_all + b0 * TJ;
        const int*   labj = labj_all + b0 * TJ;
        const int j0 = jbase + jt * TJ;
#pragma unroll
        for (int nf = 0; nf < 2; nf++) {
            const int c0 = ncol0 + nf * 8 + 2 * t;
            const float q0 = sqj[c0], q1 = sqj[c0 + 1];
            const int lb0 = labj[c0], lb1 = labj[c0 + 1];
#pragma unroll
            for (int mf = 0; mf < 2; mf++)
#pragma unroll
                for (int hh = 0; hh < 2; hh++) {
                    const int ri = mf * 2 + hh;
                    const int irow = i0 + mrow0 + mf * 16 + hh * 8 + g;
                    float dd0 = fmaxf(si[ri] + q0 - 2.0f * acc[mf][nf][hh * 2 + 0], 0.f);
                    float dd1 = fmaxf(si[ri] + q1 - 2.0f * acc[mf][nf][hh * 2 + 1], 0.f);
                    if (lb0 != li[ri]) rmin[ri] = fminf(rmin[ri], dd0);
                    else if (j0 + c0 != irow) {
                        int slot = atomicAdd(&g_pcount, 1);
                        if (slot < PCAP) { g_pi[slot] = irow; g_pd[slot] = dd0; }
                    }
                    if (lb1 != li[ri]) rmin[ri] = fminf(rmin[ri], dd1);
                    else if (j0 + c0 + 1 != irow) {
                        int slot = atomicAdd(&g_pcount, 1);
                        if (slot < PCAP) { g_pi[slot] = irow; g_pd[slot] = dd1; }
                    }
                }
        }
        __syncthreads();   // protect buffer b0 before refill at jt+2
    }

    // ---- final min reduction ----
#pragma unroll
    for (int h = 0; h < 4; h++) {
        rmin[h] = fminf(rmin[h], __shfl_xor_sync(0xffffffffu, rmin[h], 1));
        rmin[h] = fminf(rmin[h], __shfl_xor_sync(0xffffffffu, rmin[h], 2));
    }
    if (t == 0) {
#pragma unroll
        for (int mf = 0; mf < 2; mf++)
#pragma unroll
            for (int hh = 0; hh < 2; hh++) {
                int rloc = mrow0 + mf * 16 + hh * 8 + g;
                atomicMin(&smin[rloc], __float_as_uint(rmin[mf * 2 + hh]));
            }
    }
    __syncthreads();
    if (tid < 128) atomicMin(&g_negmin[i0 + tid], smin[tid]);
}

// ---------------- positives finish (block-aggregated atomics) ----------------
__global__ void pos_finish_kernel() {
    __shared__ float ssum;
    __shared__ int   scnt;
    if (threadIdx.x == 0) { ssum = 0.f; scnt = 0; }
    __syncthreads();

    int idx = blockIdx.x * blockDim.x + threadIdx.x;
    int n = min(g_pcount, PCAP);
    float lsum = 0.f;
    int   lcnt = 0;
    if (idx < n) {
        int i = g_pi[idx];
        unsigned nb = g_negmin[i];
        if (nb != 0x7f800000u) {
            float hn = __uint_as_float(nb);
            float dpos = g_pd[idx];
            if (hn < dpos) { lsum = dpos - hn + TMARGIN; lcnt = 1; }
        }
    }
#pragma unroll
    for (int off = 16; off; off >>= 1) {
        lsum += __shfl_xor_sync(0xffffffffu, lsum, off);
        lcnt += __shfl_xor_sync(0xffffffffu, lcnt, off);
    }
    if ((threadIdx.x & 31) == 0 && lcnt) {
        atomicAdd(&ssum, lsum);
        atomicAdd(&scnt, lcnt);
    }
    __syncthreads();
    if (threadIdx.x == 0 && scnt) {
        atomicAdd(&g_total, ssum);
        atomicAdd(&g_count, scnt);
    }
}

__global__ void fin_kernel(float* out, int n) {
    float c = (float)g_count;
    float loss = g_total / fmaxf(c, 1.f);
    if (n >= 1) out[0] = loss;
    if (n >= 2) out[1] = c;
}

extern "C" void kernel_launch(void* const* d_in, const int* in_sizes, int n_in,
                              void* d_out, int out_size) {
    const float* E = (const float*)d_in[0];
    const void* lab = d_in[1];
    float* out = (float*)d_out;

    cudaFuncSetAttribute(negmine_kernel, cudaFuncAttributeMaxDynamicSharedMemorySize, SMEM_TOTAL);

    detect_kernel<<<1, 128>>>((const int*)lab);
    init_kernel<<<(BN + 255) / 256, 256>>>(lab);
    prep_kernel<<<BN / 8, 256>>>(E);
    dim3 g(BN / TI, JSPLIT);
    negmine_kernel<<<g, NTHREADS, SMEM_TOTAL>>>();
    pos_finish_kernel<<<PCAP / 256, 256>>>();
    fin_kernel<<<1, 1>>>(out, out_size);
}

// round 8
// speedup vs baseline: 5.9965x; 1.2829x over previous
#include <cuda_runtime.h>
#include <cuda_fp16.h>
#include <cstdint>

// ---------------- problem constants ----------------
#define BN 8192
#define DD 128
#define TMARGIN 1.0f

// ---------------- tiling ----------------
#define TI 128
#define TJ 64
#define NTJ (BN / TJ)              // 128 j-tiles
#define TOTAL_TILES ((BN / TI) * NTJ)  // 8192
#define GRIDN 444                  // 148 SMs x 3 CTAs
#define PITCH 272                  // 256B data + 16B pad -> conflict-free ldmatrix
#define ATILEB (128 * PITCH)       // 34816
#define BTILEB (TJ * PITCH)        // 17408
#define PCAP (1 << 18)
#define NTHREADS 256

// ---------------- device globals ----------------
__device__ float        g_sq[BN];
__device__ unsigned int g_negmin[BN];
__device__ float        g_total;
__device__ int          g_count;
__device__ int          g_lab32[BN];
__device__ __half       g_H[BN * DD];
__device__ int          g_pcount;
__device__ int          g_pi[PCAP];
__device__ float        g_pd[PCAP];

// ---------------- PTX helpers (baseline, legal at target sm_103) ----------------
__device__ __forceinline__ uint32_t smem_u32(const void* p) {
    uint32_t a;
    asm("{ .reg .u64 t; cvta.to.shared.u64 t, %1; cvt.u32.u64 %0, t; }" : "=r"(a) : "l"(p));
    return a;
}
#define CP_ASYNC16(dst, src) \
    asm volatile("cp.async.cg.shared.global [%0], [%1], 16;" :: "r"(dst), "l"(src))
#define CP_COMMIT() asm volatile("cp.async.commit_group;")
#define CP_WAIT1()  asm volatile("cp.async.wait_group 1;")
#define CP_WAIT0()  asm volatile("cp.async.wait_group 0;")

#define LDSM_X4(r0, r1, r2, r3, addr) \
    asm volatile("ldmatrix.sync.aligned.m8n8.x4.shared.b16 {%0,%1,%2,%3}, [%4];" \
                 : "=r"(r0), "=r"(r1), "=r"(r2), "=r"(r3) : "r"(addr))

#define MMA16816(d, a0, a1, a2, a3, b0, b1) \
    asm volatile("mma.sync.aligned.m16n8k16.row.col.f32.f16.f16.f32 " \
                 "{%0,%1,%2,%3}, {%4,%5,%6,%7}, {%8,%9}, {%0,%1,%2,%3};" \
                 : "+f"((d)[0]), "+f"((d)[1]), "+f"((d)[2]), "+f"((d)[3]) \
                 : "r"(a0), "r"(a1), "r"(a2), "r"(a3), "r"(b0), "r"(b1))

// ---------------- SMEM layout ----------------
#define OFF_A    0
#define OFF_B    ATILEB                      // 2 buffers of BTILEB
#define OFF_SQJ  (ATILEB + 2 * BTILEB)       // float [2][TJ]
#define OFF_LABJ (OFF_SQJ + 2 * TJ * 4)      // int   [2][TJ]
#define OFF_SMIN (OFF_LABJ + 2 * TJ * 4)     // uint  [128]
#define SMEM_TOTAL (OFF_SMIN + 512)          // ~71.2 KB -> 3 CTAs/SM

// ---------------- small kernels ----------------
__global__ void init_kernel(const void* __restrict__ labraw) {
    // per-block int64 detection: labels < 1024 => odd 32-bit words all zero
    __shared__ int s_any;
    if (threadIdx.x == 0) s_any = 0;
    __syncthreads();
    if (threadIdx.x < 128) {
        int v = ((const int*)labraw)[2 * threadIdx.x + 1];
        unsigned any = __ballot_sync(0xffffffffu, v != 0);
        if ((threadIdx.x & 31) == 0 && any) atomicOr(&s_any, 1);
    }
    __syncthreads();
    const int is64 = (s_any == 0);

    int i = blockIdx.x * blockDim.x + threadIdx.x;
    if (i < BN) {
        g_negmin[i] = 0x7f800000u;
        g_lab32[i] = is64 ? (int)((const long long*)labraw)[i] : ((const int*)labraw)[i];
    }
    if (i == 0) { g_total = 0.f; g_count = 0; g_pcount = 0; }
}

__global__ void prep_kernel(const float* __restrict__ E) {
    int warp = (blockIdx.x * blockDim.x + threadIdx.x) >> 5;
    int lane = threadIdx.x & 31;
    if (warp >= BN) return;
    const float* row = E + (size_t)warp * DD;
    __half* hrow = g_H + (size_t)warp * DD;
    float s = 0.f;
#pragma unroll
    for (int q = 0; q < 4; q++) {
        float v = row[lane + 32 * q];
        hrow[lane + 32 * q] = __float2half(v);
        s += v * v;
    }
#pragma unroll
    for (int off = 16; off; off >>= 1) s += __shfl_xor_sync(0xffffffffu, s, off);
    if (lane == 0) g_sq[warp] = s;
}

// ---------------- HMMA fused Gram + masked-min + positive emission ----------------
// Persistent: 444 CTAs, each owns a contiguous range of the 8192 (i,j)-tile space
// (j-major within i). 8 warps, warp tile 32x32, CTA tile 128x64, 3 CTAs/SM.
__global__ __launch_bounds__(NTHREADS, 3) void negmine_kernel() {
    extern __shared__ char smem[];
    const uint32_t sb = smem_u32(smem);
    const int tid = threadIdx.x;
    const int w = tid >> 5, lane = tid & 31;
    const int g = lane >> 2, t4 = lane & 3;

    const int mrow0 = (w & 3) * 32;
    const int ncol0 = (w >> 2) * 32;

    const int blk = blockIdx.x;
    const int t0 = (TOTAL_TILES * blk) / GRIDN;
    const int t1 = (TOTAL_TILES * (blk + 1)) / GRIDN;

    float* sqj_all  = reinterpret_cast<float*>(smem + OFF_SQJ);
    int*   labj_all = reinterpret_cast<int*>(smem + OFF_LABJ);
    unsigned* smin  = reinterpret_cast<unsigned*>(smem + OFF_SMIN);

    int cur_it = t0 >> 7;          // 128 j-tiles per i-tile
    int i0 = cur_it * TI;

    // ---- prologue: A(cur_it) + B(t0) ----
#pragma unroll
    for (int c = tid; c < 2048; c += NTHREADS) {
        int row = c >> 4, col = c & 15;
        CP_ASYNC16(sb + OFF_A + row * PITCH + col * 16,
                   (const void*)(g_H + (size_t)(i0 + row) * DD + col * 8));
    }
    {
        const int j0 = (t0 & (NTJ - 1)) * TJ;
#pragma unroll
        for (int c = tid; c < 1024; c += NTHREADS) {
            int row = c >> 4, col = c & 15;
            CP_ASYNC16(sb + OFF_B + row * PITCH + col * 16,
                       (const void*)(g_H + (size_t)(j0 + row) * DD + col * 8));
        }
        CP_COMMIT();
        if (tid < TJ) {
            sqj_all[tid]  = g_sq[j0 + tid];
            labj_all[tid] = g_lab32[j0 + tid];
        }
    }
    if (tid < 128) smin[tid] = 0x7f800000u;
    CP_WAIT0();
    __syncthreads();

    // ---- per-lane ldmatrix bases ----
    uint32_t abase[2];
#pragma unroll
    for (int mf = 0; mf < 2; mf++)
        abase[mf] = sb + OFF_A
                  + (uint32_t)((mrow0 + mf * 16 + ((lane >> 3) & 1) * 8 + (lane & 7)) * PITCH)
                  + (uint32_t)((lane >> 4) * 16);
    uint32_t bbase[2];
#pragma unroll
    for (int p = 0; p < 2; p++)
        bbase[p] = sb + OFF_B
                 + (uint32_t)((ncol0 + p * 16 + ((lane >> 4) & 1) * 8 + (lane & 7)) * PITCH)
                 + (uint32_t)(((lane >> 3) & 1) * 16);

    // ---- per-i row constants ----
    float si[4]; int li[4];
#pragma unroll
    for (int mf = 0; mf < 2; mf++)
#pragma unroll
        for (int hh = 0; hh < 2; hh++) {
            int r = mrow0 + mf * 16 + hh * 8 + g;
            si[mf * 2 + hh] = g_sq[i0 + r];
            li[mf * 2 + hh] = g_lab32[i0 + r];
        }
    float rmin[4];
#pragma unroll
    for (int h = 0; h < 4; h++) rmin[h] = __int_as_float(0x7f800000);

    // ---- main persistent loop ----
    for (int t = t0; t < t1; t++) {
        const int lidx = t - t0;
        const int b0 = lidx & 1;
        const int j0 = (t & (NTJ - 1)) * TJ;
        const bool last = (t + 1 == t1);
        const bool ichange = !last && ((t + 1) >> 7) != cur_it;

        // [1] prefetch next B
        if (!last) {
            const int b1 = b0 ^ 1;
            const int j1 = ((t + 1) & (NTJ - 1)) * TJ;
#pragma unroll
            for (int c = tid; c < 1024; c += NTHREADS) {
                int row = c >> 4, col = c & 15;
                CP_ASYNC16(sb + OFF_B + b1 * BTILEB + row * PITCH + col * 16,
                           (const void*)(g_H + (size_t)(j1 + row) * DD + col * 8));
            }
            CP_COMMIT();
            if (tid < TJ) {
                sqj_all[b1 * TJ + tid]  = g_sq[j1 + tid];
                labj_all[b1 * TJ + tid] = g_lab32[j1 + tid];
            }
            CP_WAIT1();
        } else {
            CP_WAIT0();
        }
        __syncthreads();

        // [2] compute: 8 k-steps x (2A + 2B LDSM, 8 MMA)
        float acc[2][4][4];
#pragma unroll
        for (int mf = 0; mf < 2; mf++)
#pragma unroll
            for (int nf = 0; nf < 4; nf++)
#pragma unroll
                for (int e = 0; e < 4; e++) acc[mf][nf][e] = 0.f;

        const uint32_t bufoff = (uint32_t)(b0 * BTILEB);
#pragma unroll
        for (int ks = 0; ks < DD / 16; ks++) {
            uint32_t a0[4], a1[4], bf[2][4];
            LDSM_X4(a0[0], a0[1], a0[2], a0[3], abase[0] + ks * 32);
            LDSM_X4(a1[0], a1[1], a1[2], a1[3], abase[1] + ks * 32);
            LDSM_X4(bf[0][0], bf[0][1], bf[0][2], bf[0][3], bbase[0] + bufoff + ks * 32);
            LDSM_X4(bf[1][0], bf[1][1], bf[1][2], bf[1][3], bbase[1] + bufoff + ks * 32);
#pragma unroll
            for (int nf = 0; nf < 4; nf++) {
                MMA16816(acc[0][nf], a0[0], a0[1], a0[2], a0[3],
                         bf[nf >> 1][(nf & 1) * 2], bf[nf >> 1][(nf & 1) * 2 + 1]);
                MMA16816(acc[1][nf], a1[0], a1[1], a1[2], a1[3],
                         bf[nf >> 1][(nf & 1) * 2], bf[nf >> 1][(nf & 1) * 2 + 1]);
            }
        }

        // [3] epilogue
        const float* sqj  = sqj_all + b0 * TJ;
        const int*   labj = labj_all + b0 * TJ;
#pragma unroll
        for (int nf = 0; nf < 4; nf++) {
            const int c0 = ncol0 + nf * 8 + 2 * t4;
            const float q0 = sqj[c0], q1 = sqj[c0 + 1];
            const int lb0 = labj[c0], lb1 = labj[c0 + 1];
#pragma unroll
            for (int mf = 0; mf < 2; mf++)
#pragma unroll
                for (int hh = 0; hh < 2; hh++) {
                    const int ri = mf * 2 + hh;
                    const int irow = i0 + mrow0 + mf * 16 + hh * 8 + g;
                    float dd0 = fmaxf(si[ri] + q0 - 2.0f * acc[mf][nf][hh * 2 + 0], 0.f);
                    float dd1 = fmaxf(si[ri] + q1 - 2.0f * acc[mf][nf][hh * 2 + 1], 0.f);
                    if (lb0 != li[ri]) rmin[ri] = fminf(rmin[ri], dd0);
                    else if (j0 + c0 != irow) {
                        int slot = atomicAdd(&g_pcount, 1);
                        if (slot < PCAP) { g_pi[slot] = irow; g_pd[slot] = dd0; }
                    }
                    if (lb1 != li[ri]) rmin[ri] = fminf(rmin[ri], dd1);
                    else if (j0 + c0 + 1 != irow) {
                        int slot = atomicAdd(&g_pcount, 1);
                        if (slot < PCAP) { g_pi[slot] = irow; g_pd[slot] = dd1; }
                    }
                }
        }
        __syncthreads();   // buffer b0 safe for refill; smin stable

        // [4] i-tile boundary: flush rmin, reload A and row constants
        if (ichange) {
#pragma unroll
            for (int h = 0; h < 4; h++) {
                rmin[h] = fminf(rmin[h], __shfl_xor_sync(0xffffffffu, rmin[h], 1));
                rmin[h] = fminf(rmin[h], __shfl_xor_sync(0xffffffffu, rmin[h], 2));
            }
            if (t4 == 0) {
#pragma unroll
                for (int mf = 0; mf < 2; mf++)
#pragma unroll
                    for (int hh = 0; hh < 2; hh++)
                        atomicMin(&smin[mrow0 + mf * 16 + hh * 8 + g],
                                  __float_as_uint(rmin[mf * 2 + hh]));
            }
            __syncthreads();
            if (tid < 128) {
                atomicMin(&g_negmin[i0 + tid], smin[tid]);
                smin[tid] = 0x7f800000u;
            }

            cur_it = (t + 1) >> 7;
            i0 = cur_it * TI;
#pragma unroll
            for (int c = tid; c < 2048; c += NTHREADS) {
                int row = c >> 4, col = c & 15;
                CP_ASYNC16(sb + OFF_A + row * PITCH + col * 16,
                           (const void*)(g_H + (size_t)(i0 + row) * DD + col * 8));
            }
            CP_COMMIT();
            CP_WAIT0();
            __syncthreads();
#pragma unroll
            for (int mf = 0; mf < 2; mf++)
#pragma unroll
                for (int hh = 0; hh < 2; hh++) {
                    int r = mrow0 + mf * 16 + hh * 8 + g;
                    si[mf * 2 + hh] = g_sq[i0 + r];
                    li[mf * 2 + hh] = g_lab32[i0 + r];
                    rmin[mf * 2 + hh] = __int_as_float(0x7f800000);
                }
        }
    }

    // ---- final flush ----
#pragma unroll
    for (int h = 0; h < 4; h++) {
        rmin[h] = fminf(rmin[h], __shfl_xor_sync(0xffffffffu, rmin[h], 1));
        rmin[h] = fminf(rmin[h], __shfl_xor_sync(0xffffffffu, rmin[h], 2));
    }
    if (t4 == 0) {
#pragma unroll
        for (int mf = 0; mf < 2; mf++)
#pragma unroll
            for (int hh = 0; hh < 2; hh++)
                atomicMin(&smin[mrow0 + mf * 16 + hh * 8 + g],
                          __float_as_uint(rmin[mf * 2 + hh]));
    }
    __syncthreads();
    if (tid < 128) atomicMin(&g_negmin[i0 + tid], smin[tid]);
}

// ---------------- positives finish (grid-stride, block-aggregated) ----------------
__global__ void pos_finish_kernel() {
    __shared__ float ssum;
    __shared__ int   scnt;
    if (threadIdx.x == 0) { ssum = 0.f; scnt = 0; }
    __syncthreads();

    const int n = min(g_pcount, PCAP);
    float lsum = 0.f;
    int   lcnt = 0;
    for (int idx = blockIdx.x * blockDim.x + threadIdx.x; idx < n;
         idx += gridDim.x * blockDim.x) {
        int i = g_pi[idx];
        unsigned nb = g_negmin[i];
        if (nb != 0x7f800000u) {
            float hn = __uint_as_float(nb);
            float dpos = g_pd[idx];
            if (hn < dpos) { lsum += dpos - hn + TMARGIN; lcnt += 1; }
        }
    }
#pragma unroll
    for (int off = 16; off; off >>= 1) {
        lsum += __shfl_xor_sync(0xffffffffu, lsum, off);
        lcnt += __shfl_xor_sync(0xffffffffu, lcnt, off);
    }
    if ((threadIdx.x & 31) == 0 && lcnt) {
        atomicAdd(&ssum, lsum);
        atomicAdd(&scnt, lcnt);
    }
    __syncthreads();
    if (threadIdx.x == 0 && scnt) {
        atomicAdd(&g_total, ssum);
        atomicAdd(&g_count, scnt);
    }
}

__global__ void fin_kernel(float* out, int n) {
    float c = (float)g_count;
    float loss = g_total / fmaxf(c, 1.f);
    if (n >= 1) out[0] = loss;
    if (n >= 2) out[1] = c;
}

extern "C" void kernel_launch(void* const* d_in, const int* in_sizes, int n_in,
                              void* d_out, int out_size) {
    const float* E = (const float*)d_in[0];
    const void* lab = d_in[1];
    float* out = (float*)d_out;

    cudaFuncSetAttribute(negmine_kernel, cudaFuncAttributeMaxDynamicSharedMemorySize, SMEM_TOTAL);

    init_kernel<<<(BN + 255) / 256, 256>>>(lab);
    prep_kernel<<<BN / 8, 256>>>(E);
    negmine_kernel<<<GRIDN, NTHREADS, SMEM_TOTAL>>>();
    pos_finish_kernel<<<128, 256>>>();
    fin_kernel<<<1, 1>>>(out, out_size);
}

// round 9
// speedup vs baseline: 7.6950x; 1.2832x over previous
#include <cuda_runtime.h>
#include <cuda_fp16.h>
#include <cstdint>

// ---------------- problem constants ----------------
#define BN 8192
#define DD 128
#define TMARGIN 1.0f

// ---------------- tiling ----------------
#define TI 128
#define TJ 64
// Lower-triangle tile enumeration: for i-tile `it`, j-tiles 0..2it+1
// (2it strictly-lower + 2 diagonal-block tiles). Total = sum(2it+2) = 64*65.
#define TOTAL_TILES 4160
#define GRIDN 444                  // 148 SMs x 3 CTAs
#define PITCH 272                  // 256B data + 16B pad -> conflict-free ldmatrix
#define ATILEB (128 * PITCH)       // 34816
#define BTILEB (TJ * PITCH)        // 17408
#define PCAP (1 << 18)
#define NTHREADS 256
#define FINF 0x7f800000u

// ---------------- device globals ----------------
__device__ float        g_sq[BN];
__device__ unsigned int g_negmin[BN];
__device__ float        g_total;
__device__ int          g_count;
__device__ int          g_lab32[BN];
__device__ __half       g_H[BN * DD];
__device__ int          g_pcount;
__device__ int          g_pi[PCAP];
__device__ float        g_pd[PCAP];

// ---------------- PTX helpers (baseline, legal at target sm_103) ----------------
__device__ __forceinline__ uint32_t smem_u32(const void* p) {
    uint32_t a;
    asm("{ .reg .u64 t; cvta.to.shared.u64 t, %1; cvt.u32.u64 %0, t; }" : "=r"(a) : "l"(p));
    return a;
}
#define CP_ASYNC16(dst, src) \
    asm volatile("cp.async.cg.shared.global [%0], [%1], 16;" :: "r"(dst), "l"(src))
#define CP_COMMIT() asm volatile("cp.async.commit_group;")
#define CP_WAIT1()  asm volatile("cp.async.wait_group 1;")
#define CP_WAIT0()  asm volatile("cp.async.wait_group 0;")

#define LDSM_X4(r0, r1, r2, r3, addr) \
    asm volatile("ldmatrix.sync.aligned.m8n8.x4.shared.b16 {%0,%1,%2,%3}, [%4];" \
                 : "=r"(r0), "=r"(r1), "=r"(r2), "=r"(r3) : "r"(addr))

#define MMA16816(d, a0, a1, a2, a3, b0, b1) \
    asm volatile("mma.sync.aligned.m16n8k16.row.col.f32.f16.f16.f32 " \
                 "{%0,%1,%2,%3}, {%4,%5,%6,%7}, {%8,%9}, {%0,%1,%2,%3};" \
                 : "+f"((d)[0]), "+f"((d)[1]), "+f"((d)[2]), "+f"((d)[3]) \
                 : "r"(a0), "r"(a1), "r"(a2), "r"(a3), "r"(b0), "r"(b1))

// ---------------- SMEM layout ----------------
#define OFF_A    0
#define OFF_B    ATILEB                      // 2 buffers of BTILEB
#define OFF_SQJ  (ATILEB + 2 * BTILEB)       // float [2][TJ]
#define OFF_LABJ (OFF_SQJ + 2 * TJ * 4)      // int   [2][TJ]
#define OFF_SMIN (OFF_LABJ + 2 * TJ * 4)     // uint  [128]  (row mins)
#define OFF_CMIN (OFF_SMIN + 512)            // uint  [2][TJ] (col mins, ping-pong)
#define SMEM_TOTAL (OFF_CMIN + 2 * TJ * 4)   // ~71.7 KB -> 3 CTAs/SM

// ---------------- fused setup: label init + fp16 convert + row norms ----------------
__global__ void setup_kernel(const float* __restrict__ E, const void* __restrict__ labraw) {
    __shared__ int s_any;
    if (threadIdx.x == 0) s_any = 0;
    __syncthreads();
    // dtype detection: int64 labels < 1024 => odd 32-bit words of first 128 pairs all 0
    if (threadIdx.x < 128) {
        int v = ((const int*)labraw)[2 * threadIdx.x + 1];
        unsigned any = __ballot_sync(0xffffffffu, v != 0);
        if ((threadIdx.x & 31) == 0 && any) atomicOr(&s_any, 1);
    }

    // one warp per row: convert + squared norm
    const int warp = threadIdx.x >> 5, lane = threadIdx.x & 31;
    const int row = blockIdx.x * 8 + warp;
    const float* r = E + (size_t)row * DD;
    __half* h = g_H + (size_t)row * DD;
    float s = 0.f;
#pragma unroll
    for (int q = 0; q < 4; q++) {
        float v = r[lane + 32 * q];
        h[lane + 32 * q] = __float2half(v);
        s += v * v;
    }
#pragma unroll
    for (int off = 16; off; off >>= 1) s += __shfl_xor_sync(0xffffffffu, s, off);
    if (lane == 0) g_sq[row] = s;

    __syncthreads();
    const int is64 = (s_any == 0);
    if (threadIdx.x < 8) {
        int i = blockIdx.x * 8 + threadIdx.x;
        g_negmin[i] = FINF;
        g_lab32[i] = is64 ? (int)((const long long*)labraw)[i] : ((const int*)labraw)[i];
    }
    if (blockIdx.x == 0 && threadIdx.x == 0) { g_total = 0.f; g_count = 0; g_pcount = 0; }
}

// ---------------- HMMA fused Gram + row/col masked-min + positive emission ----------------
// Lower-triangle persistent schedule: tile f -> (it, jt) with jt = f - it*(it+1).
// Strictly-lower tiles (jt < 2*it) contribute BOTH row-mins (anchors = rows)
// and column-mins (anchors = cols), plus positive pairs in both orientations.
// Diagonal-block tiles (jt = 2it, 2it+1) contain both orderings of every pair
// inside the block: row-processing alone is complete; col emission suppressed.
__global__ __launch_bounds__(NTHREADS, 3) void negmine_kernel() {
    extern __shared__ char smem[];
    const uint32_t sb = smem_u32(smem);
    const int tid = threadIdx.x;
    const int w = tid >> 5, lane = tid & 31;
    const int g = lane >> 2, t4 = lane & 3;

    const int mrow0 = (w & 3) * 32;
    const int ncol0 = (w >> 2) * 32;

    const int blk = blockIdx.x;
    const int t0 = (TOTAL_TILES * blk) / GRIDN;
    const int t1 = (TOTAL_TILES * (blk + 1)) / GRIDN;

    float* sqj_all  = reinterpret_cast<float*>(smem + OFF_SQJ);
    int*   labj_all = reinterpret_cast<int*>(smem + OFF_LABJ);
    unsigned* smin  = reinterpret_cast<unsigned*>(smem + OFF_SMIN);
    unsigned* scol  = reinterpret_cast<unsigned*>(smem + OFF_CMIN);

    // decode i-tile of t0: it*(it+1) <= t0 < (it+1)*(it+2)
    int it = (int)((sqrtf(4.0f * (float)t0 + 1.0f) - 1.0f) * 0.5f);
    while ((it + 1) * (it + 2) <= t0) it++;
    while (it * (it + 1) > t0) it--;
    int i0 = it * TI;

    // ---- prologue: A(it) + B(t0) ----
#pragma unroll
    for (int c = tid; c < 2048; c += NTHREADS) {
        int row = c >> 4, col = c & 15;
        CP_ASYNC16(sb + OFF_A + row * PITCH + col * 16,
                   (const void*)(g_H + (size_t)(i0 + row) * DD + col * 8));
    }
    {
        const int j0 = (t0 - it * (it + 1)) * TJ;
#pragma unroll
        for (int c = tid; c < 1024; c += NTHREADS) {
            int row = c >> 4, col = c & 15;
            CP_ASYNC16(sb + OFF_B + row * PITCH + col * 16,
                       (const void*)(g_H + (size_t)(j0 + row) * DD + col * 8));
        }
        CP_COMMIT();
        if (tid < TJ) {
            sqj_all[tid]  = g_sq[j0 + tid];
            labj_all[tid] = g_lab32[j0 + tid];
        }
    }
    if (tid < 128) smin[tid] = FINF;
    if (tid < 2 * TJ) scol[tid] = FINF;
    CP_WAIT0();
    __syncthreads();

    // ---- per-lane ldmatrix bases ----
    uint32_t abase[2];
#pragma unroll
    for (int mf = 0; mf < 2; mf++)
        abase[mf] = sb + OFF_A
                  + (uint32_t)((mrow0 + mf * 16 + ((lane >> 3) & 1) * 8 + (lane & 7)) * PITCH)
                  + (uint32_t)((lane >> 4) * 16);
    uint32_t bbase[2];
#pragma unroll
    for (int p = 0; p < 2; p++)
        bbase[p] = sb + OFF_B
                 + (uint32_t)((ncol0 + p * 16 + ((lane >> 4) & 1) * 8 + (lane & 7)) * PITCH)
                 + (uint32_t)(((lane >> 3) & 1) * 16);

    // ---- per-i row constants ----
    float si[4]; int li[4];
#pragma unroll
    for (int mf = 0; mf < 2; mf++)
#pragma unroll
        for (int hh = 0; hh < 2; hh++) {
            int r = mrow0 + mf * 16 + hh * 8 + g;
            si[mf * 2 + hh] = g_sq[i0 + r];
            li[mf * 2 + hh] = g_lab32[i0 + r];
        }
    float rmin[4];
#pragma unroll
    for (int h = 0; h < 4; h++) rmin[h] = __int_as_float(FINF);

    // ---- main persistent loop ----
    for (int t = t0; t < t1; t++) {
        const int b0 = (t - t0) & 1;
        const int jt = t - it * (it + 1);
        const int j0 = jt * TJ;
        const bool do_col = (jt < 2 * it);
        const bool last = (t + 1 == t1);
        const bool ichange = !last && (t + 1 == (it + 1) * (it + 2));

        // [1] prefetch next B
        if (!last) {
            const int b1 = b0 ^ 1;
            const int itn = ichange ? it + 1 : it;
            const int j1 = ((t + 1) - itn * (itn + 1)) * TJ;
#pragma unroll
            for (int c = tid; c < 1024; c += NTHREADS) {
                int row = c >> 4, col = c & 15;
                CP_ASYNC16(sb + OFF_B + b1 * BTILEB + row * PITCH + col * 16,
                           (const void*)(g_H + (size_t)(j1 + row) * DD + col * 8));
            }
            CP_COMMIT();
            if (tid < TJ) {
                sqj_all[b1 * TJ + tid]  = g_sq[j1 + tid];
                labj_all[b1 * TJ + tid] = g_lab32[j1 + tid];
            }
            CP_WAIT1();
        } else {
            CP_WAIT0();
        }
        __syncthreads();

        // [2] compute: 8 k-steps x (2A + 2B LDSM, 8 MMA)
        float acc[2][4][4];
#pragma unroll
        for (int mf = 0; mf < 2; mf++)
#pragma unroll
            for (int nf = 0; nf < 4; nf++)
#pragma unroll
                for (int e = 0; e < 4; e++) acc[mf][nf][e] = 0.f;

        const uint32_t bufoff = (uint32_t)(b0 * BTILEB);
#pragma unroll
        for (int ks = 0; ks < DD / 16; ks++) {
            uint32_t a0[4], a1[4], bf[2][4];
            LDSM_X4(a0[0], a0[1], a0[2], a0[3], abase[0] + ks * 32);
            LDSM_X4(a1[0], a1[1], a1[2], a1[3], abase[1] + ks * 32);
            LDSM_X4(bf[0][0], bf[0][1], bf[0][2], bf[0][3], bbase[0] + bufoff + ks * 32);
            LDSM_X4(bf[1][0], bf[1][1], bf[1][2], bf[1][3], bbase[1] + bufoff + ks * 32);
#pragma unroll
            for (int nf = 0; nf < 4; nf++) {
                MMA16816(acc[0][nf], a0[0], a0[1], a0[2], a0[3],
                         bf[nf >> 1][(nf & 1) * 2], bf[nf >> 1][(nf & 1) * 2 + 1]);
                MMA16816(acc[1][nf], a1[0], a1[1], a1[2], a1[3],
                         bf[nf >> 1][(nf & 1) * 2], bf[nf >> 1][(nf & 1) * 2 + 1]);
            }
        }

        // [3] epilogue: distance + relu + row-min + col-min + positive emission
        const float* sqj  = sqj_all + b0 * TJ;
        const int*   labj = labj_all + b0 * TJ;
        float cmin[8];
#pragma unroll
        for (int k = 0; k < 8; k++) cmin[k] = __int_as_float(FINF);

#pragma unroll
        for (int nf = 0; nf < 4; nf++) {
            const int c0 = ncol0 + nf * 8 + 2 * t4;
            const float q0 = sqj[c0], q1 = sqj[c0 + 1];
            const int lb0 = labj[c0], lb1 = labj[c0 + 1];
#pragma unroll
            for (int mf = 0; mf < 2; mf++)
#pragma unroll
                for (int hh = 0; hh < 2; hh++) {
                    const int ri = mf * 2 + hh;
                    const int irow = i0 + mrow0 + mf * 16 + hh * 8 + g;
                    float dd0 = fmaxf(si[ri] + q0 - 2.0f * acc[mf][nf][hh * 2 + 0], 0.f);
                    float dd1 = fmaxf(si[ri] + q1 - 2.0f * acc[mf][nf][hh * 2 + 1], 0.f);
                    if (lb0 != li[ri]) {
                        rmin[ri] = fminf(rmin[ri], dd0);
                        cmin[nf * 2] = fminf(cmin[nf * 2], dd0);
                    } else {
                        if (j0 + c0 != irow) {
                            int slot = atomicAdd(&g_pcount, 1);
                            if (slot < PCAP) { g_pi[slot] = irow; g_pd[slot] = dd0; }
                        }
                        if (do_col) {
                            int slot = atomicAdd(&g_pcount, 1);
                            if (slot < PCAP) { g_pi[slot] = j0 + c0; g_pd[slot] = dd0; }
                        }
                    }
                    if (lb1 != li[ri]) {
                        rmin[ri] = fminf(rmin[ri], dd1);
                        cmin[nf * 2 + 1] = fminf(cmin[nf * 2 + 1], dd1);
                    } else {
                        if (j0 + c0 + 1 != irow) {
                            int slot = atomicAdd(&g_pcount, 1);
                            if (slot < PCAP) { g_pi[slot] = irow; g_pd[slot] = dd1; }
                        }
                        if (do_col) {
                            int slot = atomicAdd(&g_pcount, 1);
                            if (slot < PCAP) { g_pi[slot] = j0 + c0 + 1; g_pd[slot] = dd1; }
                        }
                    }
                }
        }

        // column reduce across the 8 g-lanes sharing each column
#pragma unroll
        for (int k = 0; k < 8; k++) {
            float v = cmin[k];
            v = fminf(v, __shfl_xor_sync(0xffffffffu, v, 4));
            v = fminf(v, __shfl_xor_sync(0xffffffffu, v, 8));
            v = fminf(v, __shfl_xor_sync(0xffffffffu, v, 16));
            cmin[k] = v;
        }
        if (lane < 4) {
#pragma unroll
            for (int k = 0; k < 8; k++) {
                int col = ncol0 + (k >> 1) * 8 + 2 * t4 + (k & 1);
                atomicMin(&scol[b0 * TJ + col], __float_as_uint(cmin[k]));
            }
        }
        __syncthreads();   // scol complete; buffer b0 safe for refill

        // per-tile column flush + re-arm (scol[b0] next used at tile t+2)
        if (tid < TJ) {
            unsigned v = scol[b0 * TJ + tid];
            if (v != FINF) atomicMin(&g_negmin[j0 + tid], v);
            scol[b0 * TJ + tid] = FINF;
        }

        // [4] i-tile boundary: flush rmin, reload A and row constants
        if (ichange) {
#pragma unroll
            for (int h = 0; h < 4; h++) {
                rmin[h] = fminf(rmin[h], __shfl_xor_sync(0xffffffffu, rmin[h], 1));
                rmin[h] = fminf(rmin[h], __shfl_xor_sync(0xffffffffu, rmin[h], 2));
            }
            if (t4 == 0) {
#pragma unroll
                for (int mf = 0; mf < 2; mf++)
#pragma unroll
                    for (int hh = 0; hh < 2; hh++)
                        atomicMin(&smin[mrow0 + mf * 16 + hh * 8 + g],
                                  __float_as_uint(rmin[mf * 2 + hh]));
            }
            __syncthreads();
            if (tid < 128) {
                atomicMin(&g_negmin[i0 + tid], smin[tid]);
                smin[tid] = FINF;
            }

            it = it + 1;
            i0 = it * TI;
#pragma unroll
            for (int c = tid; c < 2048; c += NTHREADS) {
                int row = c >> 4, col = c & 15;
                CP_ASYNC16(sb + OFF_A + row * PITCH + col * 16,
                           (const void*)(g_H + (size_t)(i0 + row) * DD + col * 8));
            }
            CP_COMMIT();
            CP_WAIT0();
            __syncthreads();
#pragma unroll
            for (int mf = 0; mf < 2; mf++)
#pragma unroll
                for (int hh = 0; hh < 2; hh++) {
                    int r = mrow0 + mf * 16 + hh * 8 + g;
                    si[mf * 2 + hh] = g_sq[i0 + r];
                    li[mf * 2 + hh] = g_lab32[i0 + r];
                    rmin[mf * 2 + hh] = __int_as_float(FINF);
                }
        }
    }

    // ---- final row flush ----
#pragma unroll
    for (int h = 0; h < 4; h++) {
        rmin[h] = fminf(rmin[h], __shfl_xor_sync(0xffffffffu, rmin[h], 1));
        rmin[h] = fminf(rmin[h], __shfl_xor_sync(0xffffffffu, rmin[h], 2));
    }
    if (t4 == 0) {
#pragma unroll
        for (int mf = 0; mf < 2; mf++)
#pragma unroll
            for (int hh = 0; hh < 2; hh++)
                atomicMin(&smin[mrow0 + mf * 16 + hh * 8 + g],
                          __float_as_uint(rmin[mf * 2 + hh]));
    }
    __syncthreads();
    if (tid < 128) atomicMin(&g_negmin[i0 + tid], smin[tid]);
}

// ---------------- positives finish (grid-stride, block-aggregated) ----------------
__global__ void pos_finish_kernel() {
    __shared__ float ssum;
    __shared__ int   scnt;
    if (threadIdx.x == 0) { ssum = 0.f; scnt = 0; }
    __syncthreads();

    const int n = min(g_pcount, PCAP);
    float lsum = 0.f;
    int   lcnt = 0;
    for (int idx = blockIdx.x * blockDim.x + threadIdx.x; idx < n;
         idx += gridDim.x * blockDim.x) {
        int i = g_pi[idx];
        unsigned nb = g_negmin[i];
        if (nb != FINF) {
            float hn = __uint_as_float(nb);
            float dpos = g_pd[idx];
            if (hn < dpos) { lsum += dpos - hn + TMARGIN; lcnt += 1; }
        }
    }
#pragma unroll
    for (int off = 16; off; off >>= 1) {
        lsum += __shfl_xor_sync(0xffffffffu, lsum, off);
        lcnt += __shfl_xor_sync(0xffffffffu, lcnt, off);
    }
    if ((threadIdx.x & 31) == 0 && lcnt) {
        atomicAdd(&ssum, lsum);
        atomicAdd(&scnt, lcnt);
    }
    __syncthreads();
    if (threadIdx.x == 0 && scnt) {
        atomicAdd(&g_total, ssum);
        atomicAdd(&g_count, scnt);
    }
}

__global__ void fin_kernel(float* out, int n) {
    float c = (float)g_count;
    float loss = g_total / fmaxf(c, 1.f);
    if (n >= 1) out[0] = loss;
    if (n >= 2) out[1] = c;
}

extern "C" void kernel_launch(void* const* d_in, const int* in_sizes, int n_in,
                              void* d_out, int out_size) {
    const float* E = (const float*)d_in[0];
    const void* lab = d_in[1];
    float* out = (float*)d_out;

    cudaFuncSetAttribute(negmine_kernel, cudaFuncAttributeMaxDynamicSharedMemorySize, SMEM_TOTAL);

    setup_kernel<<<BN / 8, 256>>>(E, lab);
    negmine_kernel<<<GRIDN, NTHREADS, SMEM_TOTAL>>>();
    pos_finish_kernel<<<256, 256>>>();
    fin_kernel<<<1, 1>>>(out, out_size);
}